// round 3
// baseline (speedup 1.0000x reference)
#include <cuda_runtime.h>
#include <math.h>
#include <stdint.h>

#define Lq 1024
#define Rr 8192
#define NBS 128
#define NTS 512

typedef unsigned long long u64;

// ---------------- scratch (device globals; no allocs allowed) ----------------
__device__ float g_atn[(size_t)Lq * Rr];     // [l][r] 32MB, L2-resident
__device__ float g_acc[12];                  // global gradient accumulators
__device__ float g_upd[12];                  // Q(9) + tr(3) broadcast
__device__ unsigned g_cnt;                   // grid barrier counter (self-resetting)
__device__ unsigned g_sense;                 // grid barrier sense

__device__ __forceinline__ float frcp(float x) {
    float y; asm("rcp.approx.f32 %0, %1;" : "=f"(y) : "f"(x)); return y;
}

// packed f32x2 helpers (sm_100+)
__device__ __forceinline__ u64 pk2(float lo, float hi) {
    u64 r; asm("mov.b64 %0, {%1, %2};" : "=l"(r) : "f"(lo), "f"(hi)); return r;
}
__device__ __forceinline__ void up2(u64 v, float& a, float& b) {
    asm("mov.b64 {%0, %1}, %2;" : "=f"(a), "=f"(b) : "l"(v));
}
__device__ __forceinline__ u64 add2(u64 a, u64 b) {
    u64 d; asm("add.rn.f32x2 %0, %1, %2;" : "=l"(d) : "l"(a), "l"(b)); return d;
}
__device__ __forceinline__ u64 mul2(u64 a, u64 b) {
    u64 d; asm("mul.rn.f32x2 %0, %1, %2;" : "=l"(d) : "l"(a), "l"(b)); return d;
}
__device__ __forceinline__ u64 fma2(u64 a, u64 b, u64 c) {
    u64 d; asm("fma.rn.f32x2 %0, %1, %2, %3;" : "=l"(d) : "l"(a), "l"(b), "l"(c)); return d;
}

// sense-reversing grid barrier; self-resetting across graph replays.
__device__ __forceinline__ void gridbar(unsigned& sense) {
    __syncthreads();
    if (threadIdx.x == 0) {
        unsigned ns = sense ^ 1u;
        __threadfence();
        unsigned old = atomicAdd(&g_cnt, 1u);
        if (old == NBS - 1u) {
            atomicExch(&g_cnt, 0u);
            asm volatile("st.release.gpu.u32 [%0], %1;" :: "l"(&g_sense), "r"(ns) : "memory");
        } else {
            unsigned v;
            do {
                asm volatile("ld.acquire.gpu.u32 %0, [%1];" : "=r"(v) : "l"(&g_sense) : "memory");
            } while (v != ns);
        }
    }
    __syncthreads();
    sense ^= 1u;
}

// LAPACK-convention Householder QR of a 3x3 (geqrf+orgqr signs).
__device__ void qr3(const float* A, float* Q, float* Rm) {
    float M[9];
    #pragma unroll
    for (int i = 0; i < 9; i++) M[i] = A[i];
    float Qa[9] = {1.f,0.f,0.f, 0.f,1.f,0.f, 0.f,0.f,1.f};
    #pragma unroll
    for (int k = 0; k < 2; k++) {
        float alpha = M[k*3+k];
        float xn2 = 0.f;
        for (int j = k+1; j < 3; j++) xn2 += M[j*3+k]*M[j*3+k];
        if (xn2 == 0.f) continue;
        float nrm  = sqrtf(alpha*alpha + xn2);
        float beta = (alpha >= 0.f) ? -nrm : nrm;
        float v[3] = {0.f,0.f,0.f};
        v[k] = 1.f;
        float denom = alpha - beta;
        for (int j = k+1; j < 3; j++) v[j] = M[j*3+k] / denom;
        float tau = (beta - alpha) / beta;
        for (int c = k; c < 3; c++) {
            float s = 0.f;
            for (int j = k; j < 3; j++) s += v[j]*M[j*3+c];
            s *= tau;
            for (int j = k; j < 3; j++) M[j*3+c] -= s*v[j];
        }
        M[k*3+k] = beta;
        for (int j = k+1; j < 3; j++) M[j*3+k] = 0.f;
        for (int i = 0; i < 3; i++) {
            float s = 0.f;
            for (int j = k; j < 3; j++) s += Qa[i*3+j]*v[j];
            s *= tau;
            for (int j = k; j < 3; j++) Qa[i*3+j] -= s*v[j];
        }
    }
    #pragma unroll
    for (int i = 0; i < 9; i++) { Q[i] = Qa[i]; Rm[i] = M[i]; }
}

__device__ __forceinline__ float blockSum(float v, float* s16) {
    #pragma unroll
    for (int o = 16; o > 0; o >>= 1) v += __shfl_down_sync(0xffffffffu, v, o);
    __syncthreads();
    if ((threadIdx.x & 31) == 0) s16[threadIdx.x >> 5] = v;
    __syncthreads();
    float t = s16[0];
    #pragma unroll
    for (int i = 1; i < 16; i++) t += s16[i];
    return t;
}

// ---------------- atn[l][r] = dot(lig_feat[l], rec_feat[r]) -------------------
// k-packed f32x2 GEMM: block tile 128l x 64r, thread tile 8l x 4r, no transpose.
#define PAD 68   // row stride in floats (8B aligned, 2-way max bank conflict)
__global__ void __launch_bounds__(256, 2) k_atn(const float* __restrict__ lig_feat,
                                                const float* __restrict__ rec_feat) {
    extern __shared__ float smf[];
    float* slig = smf;                 // [128][PAD]
    float* srec = smf + 128*PAD;       // [64][PAD]
    int tid = threadIdx.x;
    int tx = tid & 15;                 // r-group: 4 r's at tx*4
    int ty = tid >> 4;                 // l-group: 8 l's at ty*8
    int r0b = blockIdx.x * 64;
    int l0b = blockIdx.y * 128;
    const float4* ligf4 = (const float4*)lig_feat;
    const float4* recf4 = (const float4*)rec_feat;
    #pragma unroll
    for (int i = 0; i < 8; i++) {
        int idx = i*256 + tid;
        int row = idx >> 4, f4 = idx & 15;
        *(float4*)&slig[row*PAD + f4*4] = ligf4[(size_t)(l0b+row)*16 + f4];
    }
    #pragma unroll
    for (int i = 0; i < 4; i++) {
        int idx = i*256 + tid;
        int row = idx >> 4, f4 = idx & 15;
        *(float4*)&srec[row*PAD + f4*4] = recf4[(size_t)(r0b+row)*16 + f4];
    }
    __syncthreads();

    u64 acc[8][4];
    #pragma unroll
    for (int i = 0; i < 8; i++)
        #pragma unroll
        for (int j = 0; j < 4; j++) acc[i][j] = 0ull;

    const u64* lg8 = (const u64*)&slig[(ty*8)*PAD];   // row stride PAD/2 u64
    const u64* rc4 = (const u64*)&srec[(tx*4)*PAD];

    #pragma unroll 8
    for (int k2 = 0; k2 < 32; k2++) {
        u64 lg[8], rc[4];
        #pragma unroll
        for (int i = 0; i < 8; i++) lg[i] = lg8[i*(PAD/2) + k2];
        #pragma unroll
        for (int j = 0; j < 4; j++) rc[j] = rc4[j*(PAD/2) + k2];
        #pragma unroll
        for (int i = 0; i < 8; i++)
            #pragma unroll
            for (int j = 0; j < 4; j++)
                acc[i][j] = fma2(lg[i], rc[j], acc[i][j]);
    }
    #pragma unroll
    for (int i = 0; i < 8; i++) {
        float4 o;
        float lo, hi;
        up2(acc[i][0], lo, hi); o.x = lo + hi;
        up2(acc[i][1], lo, hi); o.y = lo + hi;
        up2(acc[i][2], lo, hi); o.z = lo + hi;
        up2(acc[i][3], lo, hi); o.w = lo + hi;
        *(float4*)&g_atn[(size_t)(l0b + ty*8 + i)*Rr + r0b + tx*4] = o;
    }
}

// ---------------- persistent kernel: preps + all 8 steps ----------------------
__global__ void __launch_bounds__(NTS, 1) k_steps(const float* __restrict__ lig_coord,
                                                  const float* __restrict__ rec_coord,
                                                  const float* __restrict__ pre_rot,
                                                  const float* __restrict__ trans,
                                                  float* __restrict__ out) {
    extern __shared__ float sm[];
    float4* cA = (float4*)sm;                  // [4096] {-2x0,-2x1,-2y0,-2y1}
    float4* cB = (float4*)(sm + 16384);        // [4096] {-2z0,-2z1, c0_0, c0_1}
    __shared__ float s_red[16];
    __shared__ float s_ws[16][8];
    __shared__ float s_red12[8][12];
    __shared__ float s_ligc[8][3];

    int tid = threadIdx.x, b = blockIdx.x;
    int w = tid >> 5, lane = tid & 31;
    int lp = w & 3, q = w >> 2;                // l-pair idx, r-quarter idx
    int l0 = b*8 + lp*2;                       // warp handles l0, l0+1

    unsigned sense;
    { volatile unsigned* gs = &g_sense; sense = *gs; }

    // ---- rec means ----
    float sx = 0.f, sy = 0.f, sz = 0.f;
    for (int i = tid; i < Rr; i += NTS) {
        sx += rec_coord[3*i]; sy += rec_coord[3*i+1]; sz += rec_coord[3*i+2];
    }
    float mx = blockSum(sx, s_red) * (1.f/Rr);
    float my = blockSum(sy, s_red) * (1.f/Rr);
    float mz = blockSum(sz, s_red) * (1.f/Rr);

    // ---- build c-arrays (expansion coefficients for r-pairs) ----
    for (int p = tid; p < Rr/2; p += NTS) {
        int r0 = 2*p;
        float x0 = rec_coord[3*r0]   - mx, x1 = rec_coord[3*r0+3] - mx;
        float y0 = rec_coord[3*r0+1] - my, y1 = rec_coord[3*r0+4] - my;
        float z0 = rec_coord[3*r0+2] - mz, z1 = rec_coord[3*r0+5] - mz;
        float c00 = x0*x0 + y0*y0 + z0*z0;
        float c01 = x1*x1 + y1*y1 + z1*z1;
        cA[p] = make_float4(-2.f*x0, -2.f*x1, -2.f*y0, -2.f*y1);
        cB[p] = make_float4(-2.f*z0, -2.f*z1, c00, c01);
    }

    // ---- lig means + centered coords for this block's 8 l's ----
    float lsx = 0.f, lsy = 0.f, lsz = 0.f;
    for (int i = tid; i < Lq; i += NTS) {
        lsx += lig_coord[3*i]; lsy += lig_coord[3*i+1]; lsz += lig_coord[3*i+2];
    }
    float mlx = blockSum(lsx, s_red) * (1.f/Lq);
    float mly = blockSum(lsy, s_red) * (1.f/Lq);
    float mlz = blockSum(lsz, s_red) * (1.f/Lq);
    if (tid < 8) {
        int l = b*8 + tid;
        s_ligc[tid][0] = lig_coord[3*l]   - mlx;
        s_ligc[tid][1] = lig_coord[3*l+1] - mly;
        s_ligc[tid][2] = lig_coord[3*l+2] - mlz;
    }

    // ---- init params (block 0 thread 0 owns optimizer state) ----
    float pr[9], trv[3], Q[9], Rm[9];
    if (b == 0 && tid == 0) {
        #pragma unroll
        for (int i = 0; i < 9; i++) pr[i] = pre_rot[i];
        #pragma unroll
        for (int i = 0; i < 3; i++) trv[i] = trans[i] * 4.0f;   // TRANS_DIST
        qr3(pr, Q, Rm);
        #pragma unroll
        for (int i = 0; i < 9; i++) g_upd[i] = Q[i];
        #pragma unroll
        for (int i = 0; i < 3; i++) g_upd[9+i] = trv[i];
        #pragma unroll
        for (int i = 0; i < 12; i++) g_acc[i] = 0.f;
    }
    gridbar(sense);   // g_upd/g_acc + smem c-arrays + s_ligc ready

    float lx0 = s_ligc[lp*2][0],   ly0 = s_ligc[lp*2][1],   lz0 = s_ligc[lp*2][2];
    float lx1 = s_ligc[lp*2+1][0], ly1 = s_ligc[lp*2+1][1], lz1 = s_ligc[lp*2+1][2];

    const u64* a0p = (const u64*)g_atn + (size_t)l0*(Rr/2)        + q*1024;
    const u64* a1p = (const u64*)g_atn + (size_t)(l0+1)*(Rr/2)    + q*1024;
    const ulonglong2* pA = (const ulonglong2*)cA + q*1024;
    const ulonglong2* pB = (const ulonglong2*)cB + q*1024;

    for (int s = 0; s < 8; s++) {
        // ---- forward (all lanes compute; q0-lane0 writes out) ----
        const volatile float* up = g_upd;
        float q0v=up[0],q1v=up[1],q2v=up[2],q3v=up[3],q4v=up[4],q5v=up[5],q6v=up[6],q7v=up[7],q8v=up[8];
        float t0=up[9],t1=up[10],t2=up[11];
        float nx0 = q0v*lx0 + q1v*ly0 + q2v*lz0 + t0;
        float ny0 = q3v*lx0 + q4v*ly0 + q5v*lz0 + t1;
        float nz0 = q6v*lx0 + q7v*ly0 + q8v*lz0 + t2;
        float nx1 = q0v*lx1 + q1v*ly1 + q2v*lz1 + t0;
        float ny1 = q3v*lx1 + q4v*ly1 + q5v*lz1 + t1;
        float nz1 = q6v*lx1 + q7v*ly1 + q8v*lz1 + t2;
        if (q == 0 && lane == 0) {
            float* o = out + (size_t)s*3*Lq + 3*l0;
            o[0]=nx0; o[1]=ny0; o[2]=nz0; o[3]=nx1; o[4]=ny1; o[5]=nz1;
        }
        if (s == 7) break;

        u64 X0 = pk2(nx0,nx0), Y0 = pk2(ny0,ny0), Z0 = pk2(nz0,nz0);
        u64 X1 = pk2(nx1,nx1), Y1 = pk2(ny1,ny1), Z1 = pk2(nz1,nz1);
        float b0f = nx0*nx0 + ny0*ny0 + nz0*nz0;
        float b1f = nx1*nx1 + ny1*ny1 + nz1*nz1;
        u64 B0 = pk2(b0f,b0f), B1 = pk2(b1f,b1f);

        u64 sw0 = 0ull, ax0 = 0ull, ay0 = 0ull, az0 = 0ull;
        u64 sw1 = 0ull, ax1 = 0ull, ay1 = 0ull, az1 = 0ull;
        #pragma unroll 4
        for (int it = 0; it < 32; it++) {
            int idx = it*32 + lane;
            ulonglong2 va = pA[idx];
            ulonglong2 vb = pB[idx];
            u64 A0 = a0p[idx];
            u64 A1 = a1p[idx];
            u64 c1 = va.x, c2 = va.y, c3 = vb.x, c0 = vb.y;
            // l0
            u64 d = add2(c0, B0);
            d = fma2(c3, Z0, d); d = fma2(c2, Y0, d); d = fma2(c1, X0, d);
            float dl, dh; up2(d, dl, dh);
            u64 inv = pk2(frcp(dl), frcp(dh));
            u64 i4 = mul2(inv, inv);
            u64 wv = mul2(A0, i4);
            sw0 = add2(sw0, wv);
            ax0 = fma2(wv, c1, ax0); ay0 = fma2(wv, c2, ay0); az0 = fma2(wv, c3, az0);
            // l1
            d = add2(c0, B1);
            d = fma2(c3, Z1, d); d = fma2(c2, Y1, d); d = fma2(c1, X1, d);
            up2(d, dl, dh);
            inv = pk2(frcp(dl), frcp(dh));
            i4 = mul2(inv, inv);
            wv = mul2(A1, i4);
            sw1 = add2(sw1, wv);
            ax1 = fma2(wv, c1, ax1); ay1 = fma2(wv, c2, ay1); az1 = fma2(wv, c3, az1);
        }
        float v[8], tA, tB2;
        up2(sw0, tA, tB2); v[0] = tA + tB2;
        up2(ax0, tA, tB2); v[1] = tA + tB2;
        up2(ay0, tA, tB2); v[2] = tA + tB2;
        up2(az0, tA, tB2); v[3] = tA + tB2;
        up2(sw1, tA, tB2); v[4] = tA + tB2;
        up2(ax1, tA, tB2); v[5] = tA + tB2;
        up2(ay1, tA, tB2); v[6] = tA + tB2;
        up2(az1, tA, tB2); v[7] = tA + tB2;
        #pragma unroll
        for (int k = 0; k < 8; k++)
            #pragma unroll
            for (int o = 16; o > 0; o >>= 1)
                v[k] += __shfl_down_sync(0xffffffffu, v[k], o);
        if (lane == 0)
            #pragma unroll
            for (int k = 0; k < 8; k++) s_ws[w][k] = v[k];
        __syncthreads();

        if (tid < 8) {
            int lpi = tid >> 1, sub = tid & 1, off = sub*4;
            float sw = 0.f, ax = 0.f, ay = 0.f, az = 0.f;
            #pragma unroll
            for (int qq = 0; qq < 4; qq++) {
                sw += s_ws[qq*4+lpi][off];
                ax += s_ws[qq*4+lpi][off+1];
                ay += s_ws[qq*4+lpi][off+2];
                az += s_ws[qq*4+lpi][off+3];
            }
            float lx = s_ligc[tid][0], ly = s_ligc[tid][1], lz = s_ligc[tid][2];
            float nx = q0v*lx + q1v*ly + q2v*lz + t0;
            float ny = q3v*lx + q4v*ly + q5v*lz + t1;
            float nz = q6v*lx + q7v*ly + q8v*lz + t2;
            const float Cc = -2.f / 8388608.f;
            float gx = Cc * (sw*nx + 0.5f*ax);   // ax = -2*sum(w*rcx)
            float gy = Cc * (sw*ny + 0.5f*ay);
            float gz = Cc * (sw*nz + 0.5f*az);
            s_red12[tid][0]=gx;    s_red12[tid][1]=gy;    s_red12[tid][2]=gz;
            s_red12[tid][3]=gx*lx; s_red12[tid][4]=gx*ly; s_red12[tid][5]=gx*lz;
            s_red12[tid][6]=gy*lx; s_red12[tid][7]=gy*ly; s_red12[tid][8]=gy*lz;
            s_red12[tid][9]=gz*lx; s_red12[tid][10]=gz*ly; s_red12[tid][11]=gz*lz;
        }
        __syncthreads();
        if (tid < 12) {
            float t = 0.f;
            #pragma unroll
            for (int i = 0; i < 8; i++) t += s_red12[i][tid];
            atomicAdd(&g_acc[tid], t);
            __threadfence();
        }
        gridbar(sense);   // all partials in g_acc

        if (b == 0 && tid == 0) {
            float t[12];
            #pragma unroll
            for (int k = 0; k < 12; k++) t[k] = ((volatile float*)g_acc)[k];
            float G0=t[3],G1=t[4],G2=t[5],G3=t[6],G4=t[7],G5=t[8],G6=t[9],G7=t[10],G8=t[11];
            float S10 = Q[1]*G0 + Q[4]*G3 + Q[7]*G6;
            float S01 = Q[0]*G1 + Q[3]*G4 + Q[6]*G7;
            float S20 = Q[2]*G0 + Q[5]*G3 + Q[8]*G6;
            float S02 = Q[0]*G2 + Q[3]*G5 + Q[6]*G8;
            float S21 = Q[2]*G1 + Q[5]*G4 + Q[8]*G7;
            float S12 = Q[1]*G2 + Q[4]*G5 + Q[7]*G8;
            float b10 = S10 - S01, b20 = S20 - S02, b21 = S21 - S12;
            float T10 = b10 / Rm[0];
            float T21 = b21 / Rm[4];
            float T20 = (b20 - T21*Rm[1]) / Rm[0];
            #pragma unroll
            for (int i = 0; i < 3; i++) {
                pr[i*3+0] -= Q[i*3+1]*T10 + Q[i*3+2]*T20;   // ROT_LR=1
                pr[i*3+1] -= Q[i*3+2]*T21;
            }
            #pragma unroll
            for (int i = 0; i < 3; i++) trv[i] -= 0.1f * t[i];   // TRANS_LR
            qr3(pr, Q, Rm);
            #pragma unroll
            for (int i = 0; i < 9; i++) g_upd[i] = Q[i];
            #pragma unroll
            for (int i = 0; i < 3; i++) g_upd[9+i] = trv[i];
            #pragma unroll
            for (int i = 0; i < 12; i++) g_acc[i] = 0.f;
        }
        gridbar(sense);   // updated params visible; g_acc reset
    }
}

extern "C" void kernel_launch(void* const* d_in, const int* in_sizes, int n_in,
                              void* d_out, int out_size) {
    const float* lig_feat  = (const float*)d_in[0];
    const float* rec_feat  = (const float*)d_in[1];
    const float* lig_coord = (const float*)d_in[2];
    const float* rec_coord = (const float*)d_in[3];
    const float* pre_rot   = (const float*)d_in[4];
    const float* trans     = (const float*)d_in[5];
    float* out = (float*)d_out;

    static bool attr_set = false;
    if (!attr_set) {
        cudaFuncSetAttribute(k_steps, cudaFuncAttributeMaxDynamicSharedMemorySize,
                             (Rr/2) * 8 * (int)sizeof(float));               // 128KB
        cudaFuncSetAttribute(k_atn, cudaFuncAttributeMaxDynamicSharedMemorySize,
                             (128*PAD + 64*PAD) * (int)sizeof(float));       // ~51KB
        attr_set = true;
    }

    k_atn<<<dim3(Rr/64, Lq/128), 256, (128*PAD + 64*PAD) * sizeof(float)>>>(lig_feat, rec_feat);
    k_steps<<<NBS, NTS, (Rr/2) * 8 * sizeof(float)>>>(lig_coord, rec_coord, pre_rot, trans, out);
}

// round 4
// speedup vs baseline: 1.0866x; 1.0866x over previous
#include <cuda_runtime.h>
#include <math.h>
#include <stdint.h>

#define Lq 1024
#define Rr 8192
#define NBS 128
#define NTS 512

typedef unsigned long long u64;

// ---------------- scratch (device globals; no allocs allowed) ----------------
__device__ float g_atn[(size_t)Lq * Rr];     // [l][r] 32MB, L2-resident
__device__ float g_acc[12];                  // global gradient accumulators
__device__ float g_upd[12];                  // Q(9) + tr(3) broadcast
__device__ unsigned g_cnt;                   // init gridbar counter
__device__ unsigned g_sense;                 // init gridbar sense
__device__ unsigned g_arrive;                // per-step arrival counter
__device__ unsigned g_step;                  // latest-ready-params step flag

__device__ __forceinline__ float frcp(float x) {
    float y; asm("rcp.approx.f32 %0, %1;" : "=f"(y) : "f"(x)); return y;
}
__device__ __forceinline__ u64 pk2(float lo, float hi) {
    u64 r; asm("mov.b64 %0, {%1, %2};" : "=l"(r) : "f"(lo), "f"(hi)); return r;
}
__device__ __forceinline__ void up2(u64 v, float& a, float& b) {
    asm("mov.b64 {%0, %1}, %2;" : "=f"(a), "=f"(b) : "l"(v));
}
__device__ __forceinline__ u64 add2(u64 a, u64 b) {
    u64 d; asm("add.rn.f32x2 %0, %1, %2;" : "=l"(d) : "l"(a), "l"(b)); return d;
}
__device__ __forceinline__ u64 mul2(u64 a, u64 b) {
    u64 d; asm("mul.rn.f32x2 %0, %1, %2;" : "=l"(d) : "l"(a), "l"(b)); return d;
}
__device__ __forceinline__ u64 fma2(u64 a, u64 b, u64 c) {
    u64 d; asm("fma.rn.f32x2 %0, %1, %2, %3;" : "=l"(d) : "l"(a), "l"(b), "l"(c)); return d;
}
__device__ __forceinline__ unsigned ldacq(const unsigned* p) {
    unsigned v; asm volatile("ld.acquire.gpu.u32 %0, [%1];" : "=r"(v) : "l"(p) : "memory"); return v;
}
__device__ __forceinline__ void strel(unsigned* p, unsigned v) {
    asm volatile("st.release.gpu.u32 [%0], %1;" :: "l"(p), "r"(v) : "memory");
}

// sense-reversing grid barrier (used once at init); self-resetting across replays.
__device__ __forceinline__ void gridbar(unsigned& sense) {
    __syncthreads();
    if (threadIdx.x == 0) {
        unsigned ns = sense ^ 1u;
        __threadfence();
        unsigned old = atomicAdd(&g_cnt, 1u);
        if (old == NBS - 1u) {
            atomicExch(&g_cnt, 0u);
            strel(&g_sense, ns);
        } else {
            while (ldacq(&g_sense) != ns) {}
        }
    }
    __syncthreads();
    sense ^= 1u;
}

// LAPACK-convention Householder QR of a 3x3 (geqrf+orgqr signs).
__device__ void qr3(const float* A, float* Q, float* Rm) {
    float M[9];
    #pragma unroll
    for (int i = 0; i < 9; i++) M[i] = A[i];
    float Qa[9] = {1.f,0.f,0.f, 0.f,1.f,0.f, 0.f,0.f,1.f};
    #pragma unroll
    for (int k = 0; k < 2; k++) {
        float alpha = M[k*3+k];
        float xn2 = 0.f;
        for (int j = k+1; j < 3; j++) xn2 += M[j*3+k]*M[j*3+k];
        if (xn2 == 0.f) continue;
        float nrm  = sqrtf(alpha*alpha + xn2);
        float beta = (alpha >= 0.f) ? -nrm : nrm;
        float v[3] = {0.f,0.f,0.f};
        v[k] = 1.f;
        float denom = alpha - beta;
        for (int j = k+1; j < 3; j++) v[j] = M[j*3+k] / denom;
        float tau = (beta - alpha) / beta;
        for (int c = k; c < 3; c++) {
            float s = 0.f;
            for (int j = k; j < 3; j++) s += v[j]*M[j*3+c];
            s *= tau;
            for (int j = k; j < 3; j++) M[j*3+c] -= s*v[j];
        }
        M[k*3+k] = beta;
        for (int j = k+1; j < 3; j++) M[j*3+k] = 0.f;
        for (int i = 0; i < 3; i++) {
            float s = 0.f;
            for (int j = k; j < 3; j++) s += Qa[i*3+j]*v[j];
            s *= tau;
            for (int j = k; j < 3; j++) Qa[i*3+j] -= s*v[j];
        }
    }
    #pragma unroll
    for (int i = 0; i < 9; i++) { Q[i] = Qa[i]; Rm[i] = M[i]; }
}

__device__ __forceinline__ float blockSum(float v, float* s16) {
    #pragma unroll
    for (int o = 16; o > 0; o >>= 1) v += __shfl_down_sync(0xffffffffu, v, o);
    __syncthreads();
    if ((threadIdx.x & 31) == 0) s16[threadIdx.x >> 5] = v;
    __syncthreads();
    float t = s16[0];
    #pragma unroll
    for (int i = 1; i < 16; i++) t += s16[i];
    return t;
}

// ---------------- atn[l][r] = dot(lig_feat[l], rec_feat[r]) -------------------
// (R2 proven version) tile 64l x 64r, 256 threads, 4x4 register tile, XOR swizzle.
__global__ void __launch_bounds__(256) k_atn(const float* __restrict__ lig_feat,
                                             const float* __restrict__ rec_feat) {
    __shared__ float4 ligs4[64*16];
    __shared__ float4 recs4[64*16];
    int tid = threadIdx.x;
    int tx = tid & 15;       // r-lane
    int ty = tid >> 4;       // l-group
    int r0 = blockIdx.x * 64;
    int l0 = blockIdx.y * 64;
    const float4* ligf4 = (const float4*)lig_feat;
    const float4* recf4 = (const float4*)rec_feat;
    #pragma unroll
    for (int i = 0; i < 4; i++) {
        int idx = i*256 + tid;
        int row = idx >> 4;
        int f4  = idx & 15;
        ligs4[row*16 + (f4 ^ (row & 7))] = ligf4[(size_t)(l0+row)*16 + f4];
        recs4[row*16 + (f4 ^ (row & 7))] = recf4[(size_t)(r0+row)*16 + f4];
    }
    __syncthreads();
    float acc[4][4];
    #pragma unroll
    for (int i = 0; i < 4; i++)
        #pragma unroll
        for (int j = 0; j < 4; j++) acc[i][j] = 0.f;

    #pragma unroll
    for (int f4 = 0; f4 < 16; f4++) {
        float4 a[4], b[4];
        #pragma unroll
        for (int i = 0; i < 4; i++) {
            int row = tx + 16*i;
            a[i] = recs4[row*16 + (f4 ^ (row & 7))];
        }
        #pragma unroll
        for (int j = 0; j < 4; j++) {
            int row = ty*4 + j;
            b[j] = ligs4[row*16 + (f4 ^ (row & 7))];
        }
        #pragma unroll
        for (int i = 0; i < 4; i++)
            #pragma unroll
            for (int j = 0; j < 4; j++) {
                acc[i][j] = fmaf(a[i].x, b[j].x, acc[i][j]);
                acc[i][j] = fmaf(a[i].y, b[j].y, acc[i][j]);
                acc[i][j] = fmaf(a[i].z, b[j].z, acc[i][j]);
                acc[i][j] = fmaf(a[i].w, b[j].w, acc[i][j]);
            }
    }
    #pragma unroll
    for (int j = 0; j < 4; j++) {
        size_t rowbase = (size_t)(l0 + ty*4 + j) * Rr + r0;
        #pragma unroll
        for (int i = 0; i < 4; i++)
            g_atn[rowbase + tx + 16*i] = acc[i][j];
    }
}

// process one u64 (2 r's) for both l's
#define PAIR_BODY(Av0, Av1, cx, cy, cz)                                         \
    {                                                                           \
        u64 dx = add2(X0, cx), dy = add2(Y0, cy), dz = add2(Z0, cz);            \
        u64 d = mul2(dx, dx); d = fma2(dy, dy, d); d = fma2(dz, dz, d);         \
        float dl, dh; up2(d, dl, dh);                                           \
        u64 inv = pk2(frcp(dl), frcp(dh));                                      \
        u64 i4 = mul2(inv, inv);                                                \
        u64 wv = mul2(Av0, i4);                                                 \
        sw0 = add2(sw0, wv);                                                    \
        ax0 = fma2(wv, cx, ax0); ay0 = fma2(wv, cy, ay0); az0 = fma2(wv, cz, az0); \
        dx = add2(X1, cx); dy = add2(Y1, cy); dz = add2(Z1, cz);                \
        d = mul2(dx, dx); d = fma2(dy, dy, d); d = fma2(dz, dz, d);             \
        up2(d, dl, dh);                                                         \
        inv = pk2(frcp(dl), frcp(dh));                                          \
        i4 = mul2(inv, inv);                                                    \
        wv = mul2(Av1, i4);                                                     \
        sw1 = add2(sw1, wv);                                                    \
        ax1 = fma2(wv, cx, ax1); ay1 = fma2(wv, cy, ay1); az1 = fma2(wv, cz, az1); \
    }

// ---------------- persistent kernel: preps + all 8 steps ----------------------
__global__ void __launch_bounds__(NTS, 1) k_steps(const float* __restrict__ lig_coord,
                                                  const float* __restrict__ rec_coord,
                                                  const float* __restrict__ pre_rot,
                                                  const float* __restrict__ trans,
                                                  float* __restrict__ out) {
    extern __shared__ float sm[];
    u64* cX = (u64*)sm;              // [4096] packed r-pairs of (mean - x)
    u64* cY = cX + 4096;
    u64* cZ = cY + 4096;
    __shared__ float s_red[16];
    __shared__ float s_ws[16][8];
    __shared__ float s_red12[8][12];
    __shared__ float s_ligc[8][3];

    int tid = threadIdx.x, b = blockIdx.x;
    int w = tid >> 5, lane = tid & 31;
    int lp = w & 3, q = w >> 2;                // l-pair idx (0..3), r-quarter (0..3)
    int l0 = b*8 + lp*2;                       // warp handles l0, l0+1

    unsigned sense;
    { volatile unsigned* gs = &g_sense; sense = *gs; }

    // ---- rec means ----
    float sx = 0.f, sy = 0.f, sz = 0.f;
    for (int i = tid; i < Rr; i += NTS) {
        sx += rec_coord[3*i]; sy += rec_coord[3*i+1]; sz += rec_coord[3*i+2];
    }
    float mx = blockSum(sx, s_red) * (1.f/Rr);
    float my = blockSum(sy, s_red) * (1.f/Rr);
    float mz = blockSum(sz, s_red) * (1.f/Rr);

    // ---- build negated-centered coord arrays (4 r's per thread-iter) ----
    {
        const float4* rc4 = (const float4*)rec_coord;
        ulonglong2* vX = (ulonglong2*)cX;
        ulonglong2* vY = (ulonglong2*)cY;
        ulonglong2* vZ = (ulonglong2*)cZ;
        for (int p4 = tid; p4 < Rr/4; p4 += NTS) {
            float4 f0 = rc4[3*p4], f1 = rc4[3*p4+1], f2 = rc4[3*p4+2];
            ulonglong2 ox, oy, oz;
            ox.x = pk2(mx - f0.x, mx - f0.w);  // r0.x, r1.x
            ox.y = pk2(mx - f1.z, mx - f2.y);  // r2.x, r3.x
            oy.x = pk2(my - f0.y, my - f1.x);
            oy.y = pk2(my - f1.w, my - f2.z);
            oz.x = pk2(mz - f0.z, mz - f1.y);
            oz.y = pk2(mz - f2.x, mz - f2.w);
            vX[p4] = ox; vY[p4] = oy; vZ[p4] = oz;
        }
    }

    // ---- lig means + centered coords for this block's 8 l's ----
    float lsx = 0.f, lsy = 0.f, lsz = 0.f;
    for (int i = tid; i < Lq; i += NTS) {
        lsx += lig_coord[3*i]; lsy += lig_coord[3*i+1]; lsz += lig_coord[3*i+2];
    }
    float mlx = blockSum(lsx, s_red) * (1.f/Lq);
    float mly = blockSum(lsy, s_red) * (1.f/Lq);
    float mlz = blockSum(lsz, s_red) * (1.f/Lq);
    if (tid < 8) {
        int l = b*8 + tid;
        s_ligc[tid][0] = lig_coord[3*l]   - mlx;
        s_ligc[tid][1] = lig_coord[3*l+1] - mly;
        s_ligc[tid][2] = lig_coord[3*l+2] - mlz;
    }

    // ---- init global state (block 0 thread 0 owns optimizer state) ----
    float pr[9], trv[3], Q[9], Rm[9];
    if (b == 0 && tid == 0) {
        #pragma unroll
        for (int i = 0; i < 9; i++) pr[i] = pre_rot[i];
        #pragma unroll
        for (int i = 0; i < 3; i++) trv[i] = trans[i] * 4.0f;   // TRANS_DIST
        qr3(pr, Q, Rm);
        #pragma unroll
        for (int i = 0; i < 9; i++) g_upd[i] = Q[i];
        #pragma unroll
        for (int i = 0; i < 3; i++) g_upd[9+i] = trv[i];
        #pragma unroll
        for (int i = 0; i < 12; i++) g_acc[i] = 0.f;
        g_arrive = 0u;
        g_step = 0u;
    }
    gridbar(sense);   // init state + smem ready everywhere

    float lx0 = s_ligc[lp*2][0],   ly0 = s_ligc[lp*2][1],   lz0 = s_ligc[lp*2][2];
    float lx1 = s_ligc[lp*2+1][0], ly1 = s_ligc[lp*2+1][1], lz1 = s_ligc[lp*2+1][2];

    const ulonglong2* pa0 = (const ulonglong2*)(g_atn + (size_t)l0*Rr     + q*2048);
    const ulonglong2* pa1 = (const ulonglong2*)(g_atn + (size_t)(l0+1)*Rr + q*2048);
    const ulonglong2* pX = (const ulonglong2*)cX + q*512;
    const ulonglong2* pY = (const ulonglong2*)cY + q*512;
    const ulonglong2* pZ = (const ulonglong2*)cZ + q*512;

    for (int s = 0; s < 8; s++) {
        // ---- wait for step-s params ----
        if (tid == 0) { while ((int)ldacq(&g_step) < s) {} }
        __syncthreads();

        // ---- forward ----
        const volatile float* up = g_upd;
        float q0v=up[0],q1v=up[1],q2v=up[2],q3v=up[3],q4v=up[4],q5v=up[5],q6v=up[6],q7v=up[7],q8v=up[8];
        float t0=up[9],t1=up[10],t2=up[11];
        float nx0 = q0v*lx0 + q1v*ly0 + q2v*lz0 + t0;
        float ny0 = q3v*lx0 + q4v*ly0 + q5v*lz0 + t1;
        float nz0 = q6v*lx0 + q7v*ly0 + q8v*lz0 + t2;
        float nx1 = q0v*lx1 + q1v*ly1 + q2v*lz1 + t0;
        float ny1 = q3v*lx1 + q4v*ly1 + q5v*lz1 + t1;
        float nz1 = q6v*lx1 + q7v*ly1 + q8v*lz1 + t2;
        if (q == 0 && lane == 0) {
            float* o = out + (size_t)s*3*Lq + 3*l0;
            o[0]=nx0; o[1]=ny0; o[2]=nz0; o[3]=nx1; o[4]=ny1; o[5]=nz1;
        }
        if (s == 7) break;

        u64 X0 = pk2(nx0,nx0), Y0 = pk2(ny0,ny0), Z0 = pk2(nz0,nz0);
        u64 X1 = pk2(nx1,nx1), Y1 = pk2(ny1,ny1), Z1 = pk2(nz1,nz1);
        u64 sw0 = 0ull, ax0 = 0ull, ay0 = 0ull, az0 = 0ull;
        u64 sw1 = 0ull, ax1 = 0ull, ay1 = 0ull, az1 = 0ull;

        #pragma unroll 4
        for (int it = 0; it < 16; it++) {
            int idx = it*32 + lane;
            ulonglong2 A0 = pa0[idx];
            ulonglong2 A1 = pa1[idx];
            ulonglong2 vx = pX[idx];
            ulonglong2 vy = pY[idx];
            ulonglong2 vz = pZ[idx];
            PAIR_BODY(A0.x, A1.x, vx.x, vy.x, vz.x);
            PAIR_BODY(A0.y, A1.y, vx.y, vy.y, vz.y);
        }

        float v[8], tA, tB2;
        up2(sw0, tA, tB2); v[0] = tA + tB2;
        up2(ax0, tA, tB2); v[1] = tA + tB2;
        up2(ay0, tA, tB2); v[2] = tA + tB2;
        up2(az0, tA, tB2); v[3] = tA + tB2;
        up2(sw1, tA, tB2); v[4] = tA + tB2;
        up2(ax1, tA, tB2); v[5] = tA + tB2;
        up2(ay1, tA, tB2); v[6] = tA + tB2;
        up2(az1, tA, tB2); v[7] = tA + tB2;
        #pragma unroll
        for (int k = 0; k < 8; k++)
            #pragma unroll
            for (int o = 16; o > 0; o >>= 1)
                v[k] += __shfl_down_sync(0xffffffffu, v[k], o);
        if (lane == 0)
            #pragma unroll
            for (int k = 0; k < 8; k++) s_ws[w][k] = v[k];
        __syncthreads();

        if (tid < 8) {
            int lpi = tid >> 1, sub = tid & 1, off = sub*4;
            float sw = 0.f, ax = 0.f, ay = 0.f, az = 0.f;
            #pragma unroll
            for (int qq = 0; qq < 4; qq++) {
                sw += s_ws[qq*4+lpi][off];
                ax += s_ws[qq*4+lpi][off+1];
                ay += s_ws[qq*4+lpi][off+2];
                az += s_ws[qq*4+lpi][off+3];
            }
            float lx = s_ligc[tid][0], ly = s_ligc[tid][1], lz = s_ligc[tid][2];
            float nx = q0v*lx + q1v*ly + q2v*lz + t0;
            float ny = q3v*lx + q4v*ly + q5v*lz + t1;
            float nz = q6v*lx + q7v*ly + q8v*lz + t2;
            const float Cc = -2.f / 8388608.f;     // -2/(L*R)
            float gx = Cc * (sw*nx + ax);          // ax holds -sum(w*rx)
            float gy = Cc * (sw*ny + ay);
            float gz = Cc * (sw*nz + az);
            s_red12[tid][0]=gx;    s_red12[tid][1]=gy;    s_red12[tid][2]=gz;
            s_red12[tid][3]=gx*lx; s_red12[tid][4]=gx*ly; s_red12[tid][5]=gx*lz;
            s_red12[tid][6]=gy*lx; s_red12[tid][7]=gy*ly; s_red12[tid][8]=gy*lz;
            s_red12[tid][9]=gz*lx; s_red12[tid][10]=gz*ly; s_red12[tid][11]=gz*lz;
        }
        __syncthreads();
        if (tid < 12) {
            float t = 0.f;
            #pragma unroll
            for (int i = 0; i < 8; i++) t += s_red12[i][tid];
            atomicAdd(&g_acc[tid], t);
        }
        __syncthreads();
        if (tid == 0) {
            __threadfence();
            atomicAdd(&g_arrive, 1u);
        }

        // ---- block 0: wait all, reduce, QR backward, update, publish ----
        if (b == 0 && tid == 0) {
            while (ldacq(&g_arrive) != NBS) {}
            float t[12];
            #pragma unroll
            for (int k = 0; k < 12; k++) t[k] = ((volatile float*)g_acc)[k];
            float G0=t[3],G1=t[4],G2=t[5],G3=t[6],G4=t[7],G5=t[8],G6=t[9],G7=t[10],G8=t[11];
            float S10 = Q[1]*G0 + Q[4]*G3 + Q[7]*G6;
            float S01 = Q[0]*G1 + Q[3]*G4 + Q[6]*G7;
            float S20 = Q[2]*G0 + Q[5]*G3 + Q[8]*G6;
            float S02 = Q[0]*G2 + Q[3]*G5 + Q[6]*G8;
            float S21 = Q[2]*G1 + Q[5]*G4 + Q[8]*G7;
            float S12 = Q[1]*G2 + Q[4]*G5 + Q[7]*G8;
            float b10 = S10 - S01, b20 = S20 - S02, b21 = S21 - S12;
            float T10 = b10 / Rm[0];
            float T21 = b21 / Rm[4];
            float T20 = (b20 - T21*Rm[1]) / Rm[0];
            #pragma unroll
            for (int i = 0; i < 3; i++) {
                pr[i*3+0] -= Q[i*3+1]*T10 + Q[i*3+2]*T20;   // ROT_LR=1
                pr[i*3+1] -= Q[i*3+2]*T21;
            }
            #pragma unroll
            for (int i = 0; i < 3; i++) trv[i] -= 0.1f * t[i];   // TRANS_LR
            qr3(pr, Q, Rm);
            #pragma unroll
            for (int i = 0; i < 9; i++) g_upd[i] = Q[i];
            #pragma unroll
            for (int i = 0; i < 3; i++) g_upd[9+i] = trv[i];
            #pragma unroll
            for (int i = 0; i < 12; i++) g_acc[i] = 0.f;
            *((volatile unsigned*)&g_arrive) = 0u;
            __threadfence();
            strel(&g_step, (unsigned)(s + 1));
        }
    }
}

extern "C" void kernel_launch(void* const* d_in, const int* in_sizes, int n_in,
                              void* d_out, int out_size) {
    const float* lig_feat  = (const float*)d_in[0];
    const float* rec_feat  = (const float*)d_in[1];
    const float* lig_coord = (const float*)d_in[2];
    const float* rec_coord = (const float*)d_in[3];
    const float* pre_rot   = (const float*)d_in[4];
    const float* trans     = (const float*)d_in[5];
    float* out = (float*)d_out;

    static bool attr_set = false;
    if (!attr_set) {
        cudaFuncSetAttribute(k_steps, cudaFuncAttributeMaxDynamicSharedMemorySize,
                             3 * 4096 * (int)sizeof(u64));   // 96KB
        attr_set = true;
    }

    k_atn<<<dim3(Rr/64, Lq/64), 256>>>(lig_feat, rec_feat);
    k_steps<<<NBS, NTS, 3 * 4096 * sizeof(u64)>>>(lig_coord, rec_coord, pre_rot, trans, out);
}